// round 4
// baseline (speedup 1.0000x reference)
#include <cuda_runtime.h>
#include <cstdint>
#include <cstddef>

#define T_STEPS 1024
#define BATCH   128
#define M_ROWS  (BATCH * T_STEPS)   // 131072

// Scratch (allocation-free rule: __device__ globals)
__device__ float g_z[104857600];   // [131072, 800] max
__device__ float g_ha[26214400];   // [131072, 200] max
__device__ float g_hb[26214400];   // [131072, 200] max

// ---------------------------------------------------------------- helpers
__device__ __forceinline__ float fast_tanh(float x) {
    float y;
    asm("tanh.approx.f32 %0, %1;" : "=f"(y) : "f"(x));
    return y;
}
__device__ __forceinline__ float fast_sig(float x) {
    return fmaf(fast_tanh(0.5f * x), 0.5f, 0.5f);
}
__device__ __forceinline__ unsigned long long fma2(
    unsigned long long a, unsigned long long b, unsigned long long c) {
    unsigned long long d;
    asm("fma.rn.f32x2 %0, %1, %2, %3;" : "=l"(d) : "l"(a), "l"(b), "l"(c));
    return d;
}
__device__ __forceinline__ float lo32(unsigned long long v) {
    return __uint_as_float((unsigned)v);
}
__device__ __forceinline__ float hi32(unsigned long long v) {
    return __uint_as_float((unsigned)(v >> 32));
}
__device__ __forceinline__ unsigned long long pack2(float lo, float hi) {
    unsigned long long r;
    asm("mov.b64 %0, {%1,%2};" : "=l"(r) : "f"(lo), "f"(hi));
    return r;
}
__device__ __forceinline__ uint32_t smem_u32(const void* p) {
    uint32_t a;
    asm("{ .reg .u64 t; cvta.to.shared.u64 t, %1; cvt.u32.u64 %0, t; }" : "=r"(a) : "l"(p));
    return a;
}

// cluster-scope mbarrier wait (acquire.cluster so remote DSMEM stores are visible)
__device__ __forceinline__ void mbar_wait_cluster(uint32_t mbar, uint32_t parity) {
    uint32_t done;
    asm volatile(
        "{\n\t.reg .pred p;\n\t"
        "mbarrier.try_wait.parity.acquire.cluster.shared::cta.b64 p, [%1], %2;\n\t"
        "selp.b32 %0, 1, 0, p;\n\t}"
        : "=r"(done) : "r"(mbar), "r"(parity) : "memory");
    if (!done) {
        asm volatile(
            "{\n\t.reg .pred p;\n\t"
            "W%=:\n\t"
            "mbarrier.try_wait.parity.acquire.cluster.shared::cta.b64 p, [%0], %1, 0x989680;\n\t"
            "@p bra D%=;\n\t"
            "bra W%=;\n\t"
            "D%=:\n\t}"
            :: "r"(mbar), "r"(parity) : "memory");
    }
}

// ---------------------------------------------------------------- GEMM
// C[M,N] = A[M,K] @ B[K,N] + bias.  BM=128, BN=64, BK=16, 256 thr,
// 8m x 4n per thread, m packed in f32x2, B duplicated in smem.
__global__ __launch_bounds__(256, 2) void sgemm_bias(
    const float* __restrict__ A, const float* __restrict__ B,
    const float* __restrict__ bias, float* __restrict__ C,
    int M, int N, int K)
{
    __shared__ float As[16][132];     // [k][m]
    __shared__ float Bd0[16][72];     // dup pairs for j0,j1
    __shared__ float Bd1[16][72];     // dup pairs for j2,j3

    const int tid = threadIdx.x;
    const int tx = tid & 15, ty = tid >> 4;
    const int m0 = blockIdx.y * 128, n0 = blockIdx.x * 64;
    const int a_k = tid & 15, a_m = tid >> 4;
    const int b_n = tid & 63, b_k = tid >> 6;
    const int br = b_n & 3, bb = (b_n >> 2) * 4;

    unsigned long long acc[4][4];
#pragma unroll
    for (int i = 0; i < 4; i++)
#pragma unroll
        for (int j = 0; j < 4; j++) acc[i][j] = 0ull;

    for (int k0 = 0; k0 < K; k0 += 16) {
        const int kk_a = k0 + a_k;
        const bool ka_ok = kk_a < K;
#pragma unroll
        for (int i = 0; i < 8; i++) {
            int m = a_m + 16 * i;
            As[a_k][m] = ka_ok ? A[(size_t)(m0 + m) * K + kk_a] : 0.f;
        }
#pragma unroll
        for (int i = 0; i < 4; i++) {
            int kk = b_k + 4 * i;
            int gk = k0 + kk, gn = n0 + b_n;
            float v = (gk < K && gn < N) ? B[(size_t)gk * N + gn] : 0.f;
            if (br == 0)      { Bd0[kk][bb + 0] = v; Bd0[kk][bb + 1] = v; }
            else if (br == 1) { Bd0[kk][bb + 2] = v; Bd0[kk][bb + 3] = v; }
            else if (br == 2) { Bd1[kk][bb + 0] = v; Bd1[kk][bb + 1] = v; }
            else              { Bd1[kk][bb + 2] = v; Bd1[kk][bb + 3] = v; }
        }
        __syncthreads();
#pragma unroll
        for (int kk = 0; kk < 16; kk++) {
            ulonglong2 aA = *(const ulonglong2*)&As[kk][ty * 8];
            ulonglong2 aB = *(const ulonglong2*)&As[kk][ty * 8 + 4];
            ulonglong2 b0 = *(const ulonglong2*)&Bd0[kk][tx * 4];
            ulonglong2 b1 = *(const ulonglong2*)&Bd1[kk][tx * 4];
            acc[0][0] = fma2(aA.x, b0.x, acc[0][0]);
            acc[1][0] = fma2(aA.y, b0.x, acc[1][0]);
            acc[2][0] = fma2(aB.x, b0.x, acc[2][0]);
            acc[3][0] = fma2(aB.y, b0.x, acc[3][0]);
            acc[0][1] = fma2(aA.x, b0.y, acc[0][1]);
            acc[1][1] = fma2(aA.y, b0.y, acc[1][1]);
            acc[2][1] = fma2(aB.x, b0.y, acc[2][1]);
            acc[3][1] = fma2(aB.y, b0.y, acc[3][1]);
            acc[0][2] = fma2(aA.x, b1.x, acc[0][2]);
            acc[1][2] = fma2(aA.y, b1.x, acc[1][2]);
            acc[2][2] = fma2(aB.x, b1.x, acc[2][2]);
            acc[3][2] = fma2(aB.y, b1.x, acc[3][2]);
            acc[0][3] = fma2(aA.x, b1.y, acc[0][3]);
            acc[1][3] = fma2(aA.y, b1.y, acc[1][3]);
            acc[2][3] = fma2(aB.x, b1.y, acc[2][3]);
            acc[3][3] = fma2(aB.y, b1.y, acc[3][3]);
        }
        __syncthreads();
    }

    const int nb = n0 + tx * 4;
    float bi[4];
#pragma unroll
    for (int j = 0; j < 4; j++) bi[j] = (nb + j < N) ? bias[nb + j] : 0.f;
#pragma unroll
    for (int mp = 0; mp < 4; mp++) {
        int m_lo = m0 + ty * 8 + 2 * mp;
#pragma unroll
        for (int e = 0; e < 2; e++) {
            float v0 = (e ? hi32(acc[mp][0]) : lo32(acc[mp][0])) + bi[0];
            float v1 = (e ? hi32(acc[mp][1]) : lo32(acc[mp][1])) + bi[1];
            float v2 = (e ? hi32(acc[mp][2]) : lo32(acc[mp][2])) + bi[2];
            float v3 = (e ? hi32(acc[mp][3]) : lo32(acc[mp][3])) + bi[3];
            float* cp = C + (size_t)(m_lo + e) * N + nb;
            if (nb + 3 < N) {
                *(float4*)cp = make_float4(v0, v1, v2, v3);
            } else {
                if (nb + 0 < N) cp[0] = v0;
                if (nb + 1 < N) cp[1] = v1;
                if (nb + 2 < N) cp[2] = v2;
                if (nb + 3 < N) cp[3] = v3;
            }
        }
    }
}

// ---------------------------------------------------------------- scan H=100
// 128 CTAs x 416 thr, ONE __syncthreads per step.
// Thread = (m = tid>>2, K-quarter q = tid&3). Each thread: all 4 gate dots
// over its K-quarter (weights in regs, zero-padded to even offsets
// {0,26,50,76}); z for gate q folded into lane q; shfl_xor(1),(2) merges the
// quad; lane q==0 updates c,h and writes.
__global__ __launch_bounds__(416, 1) void lstm_scan_h100(
    const float* __restrict__ Z, const float* __restrict__ Wh,
    float* __restrict__ Hout)
{
    __shared__ float hb[2][104];

    const int tid = threadIdx.x;
    const bool dotw = tid < 400;
    const int m = tid >> 2;                    // 0..103
    const int q = tid & 3;
    const int qoff = 25 * q + (q & 1);         // 0,26,50,76 (8B aligned)
    const int qend = qoff + 26 - 2 * (q & 1);  // 26,50,76,100

    unsigned long long w[4][13];
#pragma unroll
    for (int g = 0; g < 4; g++)
#pragma unroll
        for (int j = 0; j < 13; j++) {
            int k = qoff + 2 * j;
            float wl = 0.f, wh = 0.f;
            if (dotw && k < qend) {
                wl = Wh[(size_t)k * 400 + g * 100 + m];
                wh = Wh[(size_t)(k + 1) * 400 + g * 100 + m];
            }
            w[g][j] = pack2(wl, wh);
        }
    if (tid < 104) { hb[0][tid] = 0.f; hb[1][tid] = 0.f; }
    __syncthreads();

    const int row = blockIdx.x;
    const float* Zr = Z + (size_t)row * T_STEPS * 400;
    float* Ho = Hout + (size_t)row * T_STEPS * 100;
    float c = 0.f;
    float zc = dotw ? Zr[q * 100 + m] : 0.f;
    int cur = 0;

    for (int t = 0; t < T_STEPS; t++) {
        float zn = 0.f;
        if (dotw) {
            int tn = (t + 1 < T_STEPS) ? t + 1 : t;
            zn = Zr[(size_t)tn * 400 + q * 100 + m];
        }
        unsigned long long a0 = 0ull, a1 = 0ull, a2 = 0ull, a3 = 0ull;
        const unsigned long long* hp =
            (const unsigned long long*)(&hb[cur][qoff]);
#pragma unroll
        for (int j = 0; j < 13; j++) {
            unsigned long long h2 = hp[j];
            a0 = fma2(w[0][j], h2, a0);
            a1 = fma2(w[1][j], h2, a1);
            a2 = fma2(w[2][j], h2, a2);
            a3 = fma2(w[3][j], h2, a3);
        }
        float s0 = lo32(a0) + hi32(a0);
        float s1 = lo32(a1) + hi32(a1);
        float s2 = lo32(a2) + hi32(a2);
        float s3 = lo32(a3) + hi32(a3);
        if (q == 0) s0 += zc;
        else if (q == 1) s1 += zc;
        else if (q == 2) s2 += zc;
        else s3 += zc;
        s0 += __shfl_xor_sync(0xFFFFFFFFu, s0, 1);
        s0 += __shfl_xor_sync(0xFFFFFFFFu, s0, 2);
        s1 += __shfl_xor_sync(0xFFFFFFFFu, s1, 1);
        s1 += __shfl_xor_sync(0xFFFFFFFFu, s1, 2);
        s2 += __shfl_xor_sync(0xFFFFFFFFu, s2, 1);
        s2 += __shfl_xor_sync(0xFFFFFFFFu, s2, 2);
        s3 += __shfl_xor_sync(0xFFFFFFFFu, s3, 1);
        s3 += __shfl_xor_sync(0xFFFFFFFFu, s3, 2);
        int nxt = cur ^ 1;
        if (dotw && q == 0) {
            float gi = fast_sig(s0);
            float gf = fast_sig(s1);
            float gg = fast_tanh(s2);
            float go = fast_sig(s3);
            c = fmaf(gf, c, gi * gg);
            float hnew = go * fast_tanh(c);
            hb[nxt][m] = hnew;
            Ho[(size_t)t * 100 + m] = hnew;
        }
        __syncthreads();
        zc = zn;
        cur = nxt;
    }
}

// ---------------------------------------------------------------- scan H=200
// Cluster of 4 CTAs = 4 batch rows; CTA rank rk owns hidden slice
// [50rk,50rk+50) x 4 gates, weights in registers (K split in halves across
// thread pairs, merged via shfl.down 1). Cross-CTA per-step sync via DSMEM
// mbarrier (count=4, one leader arrive per CTA) instead of barrier.cluster.
__global__ __launch_bounds__(416, 1) void lstm_scan_h200(
    const float* __restrict__ Z, const float* __restrict__ Wh,
    float* __restrict__ Hout, int writeAll)
{
    __shared__ float hb[2][4][200];
    __shared__ float gact[4][200];   // [row][gate*50+mm]
    __shared__ alignas(8) unsigned long long mbar[1];

    const int tid = threadIdx.x;
    uint32_t rk;
    asm("mov.u32 %0, %%cluster_ctarank;" : "=r"(rk));
    const bool dotw = tid < 400;
    const int lc = tid >> 1;          // 0..199 (local col: gate*50+mm)
    const int half = tid & 1;
    const int g = lc / 50, mm = lc - g * 50;
    const int gcol = g * 200 + (int)rk * 50 + mm;   // column in 800-wide z

    unsigned long long w[50];
#pragma unroll
    for (int qq = 0; qq < 50; qq++) {
        float wlo = 0.f, whi = 0.f;
        if (dotw) {
            int k = half * 100 + 2 * qq;
            wlo = Wh[(size_t)k * 800 + gcol];
            whi = Wh[(size_t)(k + 1) * 800 + gcol];
        }
        w[qq] = pack2(wlo, whi);
    }
    for (int i = tid; i < 2 * 4 * 200; i += 416) ((float*)hb)[i] = 0.f;
    const uint32_t mbarA = smem_u32(&mbar[0]);
    if (tid == 0) {
        asm volatile("mbarrier.init.shared.b64 [%0], %1;"
                     :: "r"(mbarA), "r"(4u) : "memory");
    }
    __syncthreads();
    asm volatile("barrier.cluster.arrive.aligned;" ::: "memory");
    asm volatile("barrier.cluster.wait.aligned;" ::: "memory");

    const int b0 = (blockIdx.x >> 2) * 4;
    const int ur = (tid < 200) ? tid / 50 : 0;     // update role
    const int um = (tid < 200) ? tid % 50 : 0;
    const int ugm = (int)rk * 50 + um;
    float c = 0.f;

    const size_t zstride = (size_t)T_STEPS * 800;
    const float* Zbase = Z + (size_t)b0 * zstride + gcol;
    float zc0 = 0.f, zc1 = 0.f, zc2 = 0.f, zc3 = 0.f;
    if (dotw && half == 0) {
        zc0 = Zbase[0];
        zc1 = Zbase[zstride];
        zc2 = Zbase[2 * zstride];
        zc3 = Zbase[3 * zstride];
    }
    const uint32_t hbB = smem_u32(&hb[0][0][0]);
    int cur = 0;
    uint32_t ph = 0;

    for (int t = 0; t < T_STEPS; t++) {
        float zn0 = 0.f, zn1 = 0.f, zn2 = 0.f, zn3 = 0.f;
        if (dotw && half == 0) {
            size_t off = (size_t)((t + 1 < T_STEPS) ? t + 1 : t) * 800;
            zn0 = Zbase[off];
            zn1 = Zbase[zstride + off];
            zn2 = Zbase[2 * zstride + off];
            zn3 = Zbase[3 * zstride + off];
        }
        unsigned long long a0 = 0ull, a1 = 0ull, a2 = 0ull, a3 = 0ull;
        {
            const ulonglong2* hp0 = (const ulonglong2*)&hb[cur][0][half * 100];
            const ulonglong2* hp1 = (const ulonglong2*)&hb[cur][1][half * 100];
            const ulonglong2* hp2 = (const ulonglong2*)&hb[cur][2][half * 100];
            const ulonglong2* hp3 = (const ulonglong2*)&hb[cur][3][half * 100];
#pragma unroll
            for (int qq = 0; qq < 25; qq++) {
                ulonglong2 h0 = hp0[qq];
                ulonglong2 h1 = hp1[qq];
                ulonglong2 h2 = hp2[qq];
                ulonglong2 h3 = hp3[qq];
                a0 = fma2(w[2 * qq], h0.x, a0);
                a1 = fma2(w[2 * qq], h1.x, a1);
                a2 = fma2(w[2 * qq], h2.x, a2);
                a3 = fma2(w[2 * qq], h3.x, a3);
                a0 = fma2(w[2 * qq + 1], h0.y, a0);
                a1 = fma2(w[2 * qq + 1], h1.y, a1);
                a2 = fma2(w[2 * qq + 1], h2.y, a2);
                a3 = fma2(w[2 * qq + 1], h3.y, a3);
            }
        }
        float s0 = lo32(a0) + hi32(a0);
        float s1 = lo32(a1) + hi32(a1);
        float s2 = lo32(a2) + hi32(a2);
        float s3 = lo32(a3) + hi32(a3);
        float p0 = __shfl_down_sync(0xFFFFFFFFu, s0, 1);
        float p1 = __shfl_down_sync(0xFFFFFFFFu, s1, 1);
        float p2 = __shfl_down_sync(0xFFFFFFFFu, s2, 1);
        float p3 = __shfl_down_sync(0xFFFFFFFFu, s3, 1);
        if (dotw && half == 0) {
            float pre0 = zc0 + s0 + p0;
            float pre1 = zc1 + s1 + p1;
            float pre2 = zc2 + s2 + p2;
            float pre3 = zc3 + s3 + p3;
            if (g == 2) {
                gact[0][lc] = fast_tanh(pre0);
                gact[1][lc] = fast_tanh(pre1);
                gact[2][lc] = fast_tanh(pre2);
                gact[3][lc] = fast_tanh(pre3);
            } else {
                gact[0][lc] = fast_sig(pre0);
                gact[1][lc] = fast_sig(pre1);
                gact[2][lc] = fast_sig(pre2);
                gact[3][lc] = fast_sig(pre3);
            }
        }
        __syncthreads();
        int nxt = cur ^ 1;
        if (tid < 200) {
            float gi = gact[ur][um];
            float gf = gact[ur][50 + um];
            float gg = gact[ur][100 + um];
            float go = gact[ur][150 + um];
            c = fmaf(gf, c, gi * gg);
            float hnew = go * fast_tanh(c);
            if (writeAll || t == T_STEPS - 1)
                Hout[((size_t)(b0 + ur) * T_STEPS + t) * 200 + ugm] = hnew;
            uint32_t loff = hbB + (uint32_t)(((nxt * 4 + ur) * 200 + ugm) * 4);
#pragma unroll
            for (uint32_t j = 0; j < 4; j++) {
                uint32_t pa;
                asm("mapa.shared::cluster.u32 %0, %1, %2;" : "=r"(pa) : "r"(loff), "r"(j));
                asm volatile("st.shared::cluster.f32 [%0], %1;" :: "r"(pa), "f"(hnew) : "memory");
            }
        }
        __syncthreads();
        if (tid == 0) {
            asm volatile("fence.acq_rel.cluster;" ::: "memory");
#pragma unroll
            for (uint32_t j = 0; j < 4; j++) {
                uint32_t ra;
                asm("mapa.shared::cluster.u32 %0, %1, %2;" : "=r"(ra) : "r"(mbarA), "r"(j));
                asm volatile("mbarrier.arrive.release.cluster.shared::cluster.b64 _, [%0];"
                             :: "r"(ra) : "memory");
            }
        }
        mbar_wait_cluster(mbarA, ph);
        ph ^= 1;
        zc0 = zn0; zc1 = zn1; zc2 = zn2; zc3 = zn3;
        cur = nxt;
    }
}

// ---------------------------------------------------------------- dense out
__global__ __launch_bounds__(256) void dense_out(
    const float* __restrict__ Hlast, const float* __restrict__ Wd,
    const float* __restrict__ bd, float* __restrict__ out)
{
    int p = blockIdx.x * blockDim.x + threadIdx.x;
    if (p >= BATCH * 6) return;
    int b = p / 6, o = p - b * 6;
    const float* h = Hlast + ((size_t)b * T_STEPS + (T_STEPS - 1)) * 200;
    float s = bd[o];
#pragma unroll 4
    for (int k = 0; k < 200; k++) s = fmaf(h[k], Wd[k * 6 + o], s);
    out[p] = s;
}

// ---------------------------------------------------------------- launch
static void launch_scan_big(const float* Z, const float* Wh, float* Hout,
                            int writeAll)
{
    cudaLaunchConfig_t cfg = {};
    cfg.gridDim = dim3(128, 1, 1);
    cfg.blockDim = dim3(416, 1, 1);
    cfg.dynamicSmemBytes = 0;
    cfg.stream = 0;
    cudaLaunchAttribute attrs[1];
    attrs[0].id = cudaLaunchAttributeClusterDimension;
    attrs[0].val.clusterDim.x = 4;
    attrs[0].val.clusterDim.y = 1;
    attrs[0].val.clusterDim.z = 1;
    cfg.attrs = attrs;
    cfg.numAttrs = 1;
    cudaLaunchKernelEx(&cfg, lstm_scan_h200, Z, Wh, Hout, writeAll);
}

extern "C" void kernel_launch(void* const* d_in, const int* in_sizes, int n_in,
                              void* d_out, int out_size)
{
    const float* xs  = (const float*)d_in[0];
    const float* Wx0 = (const float*)d_in[1];
    const float* Wh0 = (const float*)d_in[2];
    const float* b0  = (const float*)d_in[3];
    const float* Wx1 = (const float*)d_in[4];
    const float* Wh1 = (const float*)d_in[5];
    const float* b1  = (const float*)d_in[6];
    const float* Wx2 = (const float*)d_in[7];
    const float* Wh2 = (const float*)d_in[8];
    const float* b2  = (const float*)d_in[9];
    const float* Wx3 = (const float*)d_in[10];
    const float* Wh3 = (const float*)d_in[11];
    const float* b3  = (const float*)d_in[12];
    const float* Wd  = (const float*)d_in[13];
    const float* bd  = (const float*)d_in[14];

    float *Zb, *Ha, *Hb;
    cudaGetSymbolAddress((void**)&Zb, g_z);
    cudaGetSymbolAddress((void**)&Ha, g_ha);
    cudaGetSymbolAddress((void**)&Hb, g_hb);

    // Layer 0: Din=128, H=100
    sgemm_bias<<<dim3(7, M_ROWS / 128), 256>>>(xs, Wx0, b0, Zb, M_ROWS, 400, 128);
    lstm_scan_h100<<<128, 416>>>(Zb, Wh0, Ha);
    // Layer 1: Din=100, H=100
    sgemm_bias<<<dim3(7, M_ROWS / 128), 256>>>(Ha, Wx1, b1, Zb, M_ROWS, 400, 100);
    lstm_scan_h100<<<128, 416>>>(Zb, Wh1, Hb);
    // Layer 2: Din=100, H=200
    sgemm_bias<<<dim3(13, M_ROWS / 128), 256>>>(Hb, Wx2, b2, Zb, M_ROWS, 800, 100);
    launch_scan_big(Zb, Wh2, Ha, 1);
    // Layer 3: Din=200, H=200 (only last h needed downstream)
    sgemm_bias<<<dim3(13, M_ROWS / 128), 256>>>(Ha, Wx3, b3, Zb, M_ROWS, 800, 200);
    launch_scan_big(Zb, Wh3, Hb, 0);
    // Dense head
    dense_out<<<3, 256>>>(Hb, Wd, bd, (float*)d_out);
}